// round 9
// baseline (speedup 1.0000x reference)
#include <cuda_runtime.h>
#include <cuda_fp16.h>
#include <cstdint>

#define B 64
#define IN 1024
#define ID 256
#define NC 32
#define DC 64
#define IT 64           // i per fused block
#define CH (IN / IT)    // 16 chunks

// ---------------- static scratch ---------------------------------------------
__device__ __half g_wtil[B * NC * ID];                 // w~ fp16 (1 MB)
__device__ float  g_spart[B * 8 * ID];                 // colsum partials
__device__ float  g_vpart[(size_t)B * CH * NC * ID];   // v partials (32 MB)

// ---------------- mma helper (validated rounds 2-3) --------------------------
__device__ __forceinline__ void mma_f16(float* d, const uint32_t* a, const uint32_t* b) {
    asm volatile(
        "mma.sync.aligned.m16n8k16.row.col.f32.f16.f16.f32 "
        "{%0,%1,%2,%3}, {%4,%5,%6,%7}, {%8,%9}, {%0,%1,%2,%3};"
        : "+f"(d[0]), "+f"(d[1]), "+f"(d[2]), "+f"(d[3])
        : "r"(a[0]), "r"(a[1]), "r"(a[2]), "r"(a[3]), "r"(b[0]), "r"(b[1]));
}
__device__ __forceinline__ uint32_t h2u(__half2 h) { return *reinterpret_cast<uint32_t*>(&h); }

// ---------------- column sum: s[b,d] = sum_i u[b,i,d] ------------------------
__global__ void __launch_bounds__(256) colsum_kernel(const float* __restrict__ u) {
    const int s = blockIdx.x, b = blockIdx.y, d = threadIdx.x;
    const float* p = u + ((size_t)b * IN + s * 128) * ID + d;
    float a0 = 0.f, a1 = 0.f, a2 = 0.f, a3 = 0.f;
#pragma unroll 8
    for (int i = 0; i < 128; i += 4) {
        a0 += p[(size_t)i * ID];
        a1 += p[(size_t)(i + 1) * ID];
        a2 += p[(size_t)(i + 2) * ID];
        a3 += p[(size_t)(i + 3) * ID];
    }
    g_spart[(b * 8 + s) * ID + d] = (a0 + a1) + (a2 + a3);
}

// ---------------- projection: warp-per-batch, no inner block syncs -----------
// PHASE 0: v from colsum partials. PHASE 1: v from vpart -> w~. PHASE 2: squash.
template <int PHASE>
__global__ void __launch_bounds__(256) project_kernel(const float* __restrict__ W,
                                                      float* __restrict__ out) {
    extern __shared__ float Wsh[];            // [64][256] = 64 KB
    __shared__ float o_ws[8][DC];

    const int n = blockIdx.x, bg = blockIdx.y;
    const int t = threadIdx.x, w = t >> 5, l = t & 31;

    for (int idx = t; idx < DC * ID; idx += 256)
        Wsh[idx] = W[(size_t)n * DC * ID + idx];
    __syncthreads();

    const int b = bg * 8 + w;

    // gather v: lane l owns d = l + 32m
    float v[8];
    if (PHASE == 0) {
#pragma unroll
        for (int m = 0; m < 8; m++) {
            float s = 0.f;
#pragma unroll
            for (int q = 0; q < 8; q++) s += g_spart[(b * 8 + q) * ID + l + 32 * m];
            v[m] = s * (1.0f / 32.0f);
        }
    } else {
#pragma unroll
        for (int m = 0; m < 8; m++) v[m] = 0.f;
#pragma unroll 4
        for (int c = 0; c < CH; c++) {
            const float* pp = g_vpart + (((size_t)b * CH + c) * NC + n) * ID;
#pragma unroll
            for (int m = 0; m < 8; m++) v[m] += pp[l + 32 * m];
        }
    }

    // o_dc = <W_n[dc,:], v>
#pragma unroll
    for (int dc = 0; dc < DC; dc++) {
        float p = 0.f;
#pragma unroll
        for (int m = 0; m < 8; m++) p += Wsh[dc * ID + l + 32 * m] * v[m];
#pragma unroll
        for (int off = 16; off; off >>= 1) p += __shfl_xor_sync(0xffffffffu, p, off);
        if (l == 0) o_ws[w][dc] = p;
    }
    __syncwarp();

    float p2 = o_ws[w][l] * o_ws[w][l] + o_ws[w][32 + l] * o_ws[w][32 + l];
#pragma unroll
    for (int off = 16; off; off >>= 1) p2 += __shfl_xor_sync(0xffffffffu, p2, off);
    const float tot = p2;

    if (PHASE == 2) {
        float sq = tot + 1e-7f;
        float sc = sqrtf(sq) / (0.5f + sq);
        out[((size_t)b * NC + n) * DC + l] = sc * o_ws[w][l];
        out[((size_t)b * NC + n) * DC + 32 + l] = sc * o_ws[w][32 + l];
    } else {
        const float inv = 1.0f / fmaxf(sqrtf(tot), 1e-12f);
        float acc[8];
#pragma unroll
        for (int m = 0; m < 8; m++) acc[m] = 0.f;
#pragma unroll
        for (int dc = 0; dc < DC; dc++) {
            const float od = o_ws[w][dc];
#pragma unroll
            for (int m = 0; m < 8; m++) acc[m] += Wsh[dc * ID + l + 32 * m] * od;
        }
#pragma unroll
        for (int m = 0; m < 8; m++)
            g_wtil[((size_t)b * NC + n) * ID + l + 32 * m] = __float2half_rn(acc[m] * inv);
    }
}

// ---------------- fused routing: fp16 mma logits + fp16 mma accumulation -----
// Block: (b, chunk of 64 i). smem layout (bytes):
//   u_sh  half [64][264]   @0       (33792 B)  d-contiguous, row stride 132 words
//   u_t   half [256][66]   @33792   (33792 B)  i-contiguous, col-swizzled
//   w_sh  half [32][264]   @67584   (16896 B)
//   c_sh  half [32][72]    @84480   (4608 B)   i-contiguous
//   L_sh  float[64][34]    @89088   (8704 B)
__global__ void __launch_bounds__(256, 2) fused_kernel(const float* __restrict__ u) {
    extern __shared__ char smem[];
    __half* u_sh = (__half*)smem;
    __half* u_t = (__half*)(smem + 33792);
    __half* w_sh = (__half*)(smem + 67584);
    __half* c_sh = (__half*)(smem + 84480);
    float* L_sh = (float*)(smem + 89088);

    const int chunk = blockIdx.x, b = blockIdx.y;
    const int t = threadIdx.x, w = t >> 5, l = t & 31;
    const int g = l >> 2, tig = l & 3;

    // ---- load w~ (fp16 direct): thread: n = t>>3, seg = t&7 (32 d)
    {
        const int n = t >> 3, seg = t & 7;
        const uint4* wp = (const uint4*)(g_wtil + ((size_t)b * NC + n) * ID + seg * 32);
        uint4* ws = (uint4*)&w_sh[n * 264 + seg * 32];
        ws[0] = wp[0]; ws[1] = wp[1]; ws[2] = wp[2]; ws[3] = wp[3];
    }

    // ---- load u tile (fp32 -> fp16 into BOTH layouts)
    {
        const int ipair = t >> 3, seg = t & 7;
        const float* up = u + ((size_t)b * IN + chunk * IT + ipair * 2) * ID + seg * 32;
        float4 r0[8], r1[8];
#pragma unroll
        for (int q = 0; q < 8; q++) r0[q] = ((const float4*)up)[q];
#pragma unroll
        for (int q = 0; q < 8; q++) r1[q] = ((const float4*)(up + ID))[q];

        // u_sh rows 2*ipair, 2*ipair+1 (d-contiguous)
#pragma unroll
        for (int q = 0; q < 4; q++) {
            uint4 pk;
            pk.x = h2u(__floats2half2_rn(r0[2 * q].x, r0[2 * q].y));
            pk.y = h2u(__floats2half2_rn(r0[2 * q].z, r0[2 * q].w));
            pk.z = h2u(__floats2half2_rn(r0[2 * q + 1].x, r0[2 * q + 1].y));
            pk.w = h2u(__floats2half2_rn(r0[2 * q + 1].z, r0[2 * q + 1].w));
            *(uint4*)&u_sh[(2 * ipair) * 264 + seg * 32 + q * 8] = pk;
            uint4 pk1;
            pk1.x = h2u(__floats2half2_rn(r1[2 * q].x, r1[2 * q].y));
            pk1.y = h2u(__floats2half2_rn(r1[2 * q].z, r1[2 * q].w));
            pk1.z = h2u(__floats2half2_rn(r1[2 * q + 1].x, r1[2 * q + 1].y));
            pk1.w = h2u(__floats2half2_rn(r1[2 * q + 1].z, r1[2 * q + 1].w));
            *(uint4*)&u_sh[(2 * ipair + 1) * 264 + seg * 32 + q * 8] = pk1;
        }

        // u_t: half2(u[2ip][d], u[2ip+1][d]) at word (ipair + 4*seg) & 31 of row d
        const int colw = (ipair + 4 * seg) & 31;
        const float* f0 = (const float*)r0;
        const float* f1 = (const float*)r1;
#pragma unroll
        for (int k = 0; k < 32; k++) {
            const int d = seg * 32 + k;
            ((__half2*)&u_t[d * 66])[colw] = __floats2half2_rn(f0[k], f1[k]);
        }
    }
    __syncthreads();

    // ---- logits mma: L[i,n] = sum_d u[i,d] * w~[n,d]
    // warp w: m-tile mt = w>>1 (i rows 16mt..16mt+15), n-half h = w&1 (2 n-tiles)
    {
        const int mt = w >> 1, h = w & 1;
        float f[2][4];
#pragma unroll
        for (int nt = 0; nt < 2; nt++)
#pragma unroll
            for (int r = 0; r < 4; r++) f[nt][r] = 0.f;

#pragma unroll
        for (int ks = 0; ks < 16; ks++) {
            uint32_t a[4];
            a[0] = *(const uint32_t*)&u_sh[(16 * mt + g) * 264 + (8 * ks + tig) * 2];
            a[1] = *(const uint32_t*)&u_sh[(16 * mt + 8 + g) * 264 + (8 * ks + tig) * 2];
            a[2] = *(const uint32_t*)&u_sh[(16 * mt + g) * 264 + (8 * ks + tig + 4) * 2];
            a[3] = *(const uint32_t*)&u_sh[(16 * mt + 8 + g) * 264 + (8 * ks + tig + 4) * 2];
#pragma unroll
            for (int nt = 0; nt < 2; nt++) {
                const int n0 = h * 16 + nt * 8;
                uint32_t bb[2];
                bb[0] = *(const uint32_t*)&w_sh[(n0 + g) * 264 + (8 * ks + tig) * 2];
                bb[1] = *(const uint32_t*)&w_sh[(n0 + g) * 264 + (8 * ks + tig + 4) * 2];
                mma_f16(f[nt], a, bb);
            }
        }
#pragma unroll
        for (int nt = 0; nt < 2; nt++) {
            const int n0 = h * 16 + nt * 8 + 2 * tig;
            *(float2*)&L_sh[(16 * mt + g) * 34 + n0] = make_float2(f[nt][0], f[nt][1]);
            *(float2*)&L_sh[(16 * mt + 8 + g) * 34 + n0] = make_float2(f[nt][2], f[nt][3]);
        }
    }
    __syncthreads();

    // ---- softmax over n (lane = n); warp w handles i rows 8w..8w+7
#pragma unroll
    for (int r8 = 0; r8 < 8; r8++) {
        const int r = w * 8 + r8;
        const float val = L_sh[r * 34 + l];
        float mx = val;
#pragma unroll
        for (int off = 16; off; off >>= 1) mx = fmaxf(mx, __shfl_xor_sync(0xffffffffu, mx, off));
        const float e = __expf(val - mx);
        float s = e;
#pragma unroll
        for (int off = 16; off; off >>= 1) s += __shfl_xor_sync(0xffffffffu, s, off);
        c_sh[l * 72 + r] = __float2half_rn(e / s);   // c_sh[n][i]
    }
    __syncthreads();

    // ---- accumulation mma: V[d,n] = sum_i u_t[d,i] * c[n,i]
    // warp w: m-tiles 2w, 2w+1 (d rows 32w..32w+31); all 4 n-tiles; K=64 (4 steps)
    {
        float vfr[2][4][4];
#pragma unroll
        for (int s = 0; s < 2; s++)
#pragma unroll
            for (int nt = 0; nt < 4; nt++)
#pragma unroll
                for (int r = 0; r < 4; r++) vfr[s][nt][r] = 0.f;

        const int sw = 4 * (w & 7);   // u_t col swizzle: all rows of this warp have d>>5 == w
#pragma unroll
        for (int ks = 0; ks < 4; ks++) {
            const int kw0 = 8 * ks + tig, kw1 = kw0 + 4;
            uint32_t a[2][4];
#pragma unroll
            for (int s = 0; s < 2; s++) {
                const int dr0 = 32 * w + 16 * s + g;
                a[s][0] = *(const uint32_t*)&u_t[dr0 * 66 + (((kw0 + sw) & 31) << 1)];
                a[s][1] = *(const uint32_t*)&u_t[(dr0 + 8) * 66 + (((kw0 + sw) & 31) << 1)];
                a[s][2] = *(const uint32_t*)&u_t[dr0 * 66 + (((kw1 + sw) & 31) << 1)];
                a[s][3] = *(const uint32_t*)&u_t[(dr0 + 8) * 66 + (((kw1 + sw) & 31) << 1)];
            }
#pragma unroll
            for (int nt = 0; nt < 4; nt++) {
                uint32_t bb[2];
                bb[0] = *(const uint32_t*)&c_sh[(8 * nt + g) * 72 + (8 * ks + tig) * 2];
                bb[1] = *(const uint32_t*)&c_sh[(8 * nt + g) * 72 + (8 * ks + tig + 4) * 2];
                mma_f16(vfr[0][nt], a[0], bb);
                mma_f16(vfr[1][nt], a[1], bb);
            }
        }

        // store: frag (r0,r1) at (d, n0),(d, n0+1); (r2,r3) at d+8
        float* vp = g_vpart + (((size_t)b * CH + chunk) * NC) * ID;
#pragma unroll
        for (int s = 0; s < 2; s++) {
            const int d0 = 32 * w + 16 * s + g;
#pragma unroll
            for (int nt = 0; nt < 4; nt++) {
                const int n0 = 8 * nt + 2 * tig;
                vp[(size_t)n0 * ID + d0] = vfr[s][nt][0];
                vp[(size_t)(n0 + 1) * ID + d0] = vfr[s][nt][1];
                vp[(size_t)n0 * ID + d0 + 8] = vfr[s][nt][2];
                vp[(size_t)(n0 + 1) * ID + d0 + 8] = vfr[s][nt][3];
            }
        }
    }
}

// ---------------- launch ------------------------------------------------------
extern "C" void kernel_launch(void* const* d_in, const int* in_sizes, int n_in,
                              void* d_out, int out_size) {
    (void)in_sizes; (void)n_in; (void)out_size;
    const float* u = (const float*)d_in[0];   // [64, 1024, 256] fp32
    const float* W = (const float*)d_in[1];   // [2048, 256] fp32
    float* out = (float*)d_out;               // [64, 32, 64] fp32

    const int wbytes = DC * ID * (int)sizeof(float);  // 64 KB
    const int fbytes = 97792;                          // fused smem
    static int attr_done = 0;
    if (!attr_done) {
        cudaFuncSetAttribute(project_kernel<0>, cudaFuncAttributeMaxDynamicSharedMemorySize, wbytes);
        cudaFuncSetAttribute(project_kernel<1>, cudaFuncAttributeMaxDynamicSharedMemorySize, wbytes);
        cudaFuncSetAttribute(project_kernel<2>, cudaFuncAttributeMaxDynamicSharedMemorySize, wbytes);
        cudaFuncSetAttribute(fused_kernel, cudaFuncAttributeMaxDynamicSharedMemorySize, fbytes);
        attr_done = 1;
    }

    colsum_kernel<<<dim3(8, B), 256>>>(u);                       // s = sum_i u
    project_kernel<0><<<dim3(NC, 8), 256, wbytes>>>(W, out);     // o0 -> w~0
    fused_kernel<<<dim3(CH, B), 256, fbytes>>>(u);               // iter 1 -> v1
    project_kernel<1><<<dim3(NC, 8), 256, wbytes>>>(W, out);     // o1 -> w~1
    fused_kernel<<<dim3(CH, B), 256, fbytes>>>(u);               // iter 2 -> v2
    project_kernel<2><<<dim3(NC, 8), 256, wbytes>>>(W, out);     // squash -> out
}

// round 11
// speedup vs baseline: 1.0559x; 1.0559x over previous
#include <cuda_runtime.h>
#include <cuda_fp16.h>
#include <cstdint>

#define B 64
#define IN 1024
#define ID 256
#define NC 32
#define DC 64

// ---------------- static scratch ---------------------------------------------
__device__ __half g_uh[(size_t)B * IN * ID];          // u fp16 [b,i,d]   32 MB
__device__ __half g_ut[(size_t)B * ID * IN];          // u fp16 [b,d,i]   32 MB
__device__ float  g_spart[B * 16 * ID];               // colsum partials
__device__ __half g_s[B * ID];                        // colsum fp16
__device__ __half g_wtil[B * NC * ID];                // w~ fp16
__device__ float  g_vpart[(size_t)B * 4 * NC * ID];   // v partials  8 MB

// ---------------- helpers ----------------------------------------------------
__device__ __forceinline__ void mma_f16(float* d, const uint32_t* a, const uint32_t* b) {
    asm volatile(
        "mma.sync.aligned.m16n8k16.row.col.f32.f16.f16.f32 "
        "{%0,%1,%2,%3}, {%4,%5,%6,%7}, {%8,%9}, {%0,%1,%2,%3};"
        : "+f"(d[0]), "+f"(d[1]), "+f"(d[2]), "+f"(d[3])
        : "r"(a[0]), "r"(a[1]), "r"(a[2]), "r"(a[3]), "r"(b[0]), "r"(b[1]));
}
__device__ __forceinline__ uint32_t h2u(__half2 h) { return *reinterpret_cast<uint32_t*>(&h); }

// ---------------- prep: u -> fp16 both layouts + colsum partials --------------
__global__ void __launch_bounds__(256, 2) prep_kernel(const float* __restrict__ u) {
    __shared__ __half tsh[256 * 66];                 // transposed tile, swizzled
    const int ib = blockIdx.x, b = blockIdx.y;
    const int t = threadIdx.x;
    const int p = t >> 3, seg = t & 7;               // i-pair p, d-group seg
    const int i0 = ib * 64;

    const float* src = u + ((size_t)b * IN + i0 + 2 * p) * ID + seg * 32;
    float4 q0[8], q1[8];
#pragma unroll
    for (int r = 0; r < 8; r++) q0[r] = ((const float4*)src)[r];
#pragma unroll
    for (int r = 0; r < 8; r++) q1[r] = ((const float4*)(src + ID))[r];

    // g_uh rows 2p, 2p+1
    {
        uint32_t ha[16], hb[16];
#pragma unroll
        for (int r = 0; r < 8; r++) {
            ha[2 * r]     = h2u(__floats2half2_rn(q0[r].x, q0[r].y));
            ha[2 * r + 1] = h2u(__floats2half2_rn(q0[r].z, q0[r].w));
            hb[2 * r]     = h2u(__floats2half2_rn(q1[r].x, q1[r].y));
            hb[2 * r + 1] = h2u(__floats2half2_rn(q1[r].z, q1[r].w));
        }
        uint4* d0 = (uint4*)(g_uh + ((size_t)b * IN + i0 + 2 * p) * ID + seg * 32);
        uint4* d1 = (uint4*)(g_uh + ((size_t)b * IN + i0 + 2 * p + 1) * ID + seg * 32);
#pragma unroll
        for (int q = 0; q < 4; q++) {
            d0[q] = make_uint4(ha[4 * q], ha[4 * q + 1], ha[4 * q + 2], ha[4 * q + 3]);
            d1[q] = make_uint4(hb[4 * q], hb[4 * q + 1], hb[4 * q + 2], hb[4 * q + 3]);
        }
    }

    // transposed swizzled tile: word p of row d at col (p + 4*(d>>5)) & 31
    const int colw = (p + 4 * seg) & 31;
#pragma unroll
    for (int r = 0; r < 8; r++) {
        const int d = seg * 32 + 4 * r;
        ((__half2*)&tsh[(d + 0) * 66])[colw] = __floats2half2_rn(q0[r].x, q1[r].x);
        ((__half2*)&tsh[(d + 1) * 66])[colw] = __floats2half2_rn(q0[r].y, q1[r].y);
        ((__half2*)&tsh[(d + 2) * 66])[colw] = __floats2half2_rn(q0[r].z, q1[r].z);
        ((__half2*)&tsh[(d + 3) * 66])[colw] = __floats2half2_rn(q0[r].w, q1[r].w);
    }
    __syncthreads();

    // un-swizzle row d = t -> g_ut (plain i-order) + colsum
    {
        const int d = t;
        const int rot = 4 * (d >> 5);
        uint32_t buf[32];
        float cs = 0.f;
#pragma unroll
        for (int q = 0; q < 32; q++) {
            __half2 h = ((__half2*)&tsh[d * 66])[(q + rot) & 31];
            buf[q] = h2u(h);
            float2 f = __half22float2(h);
            cs += f.x + f.y;
        }
        uint4* dst = (uint4*)(g_ut + ((size_t)b * ID + d) * IN + i0);
#pragma unroll
        for (int q = 0; q < 8; q++)
            dst[q] = make_uint4(buf[4 * q], buf[4 * q + 1], buf[4 * q + 2], buf[4 * q + 3]);
        g_spart[(b * 16 + ib) * ID + d] = cs;
    }
}

// ---------------- colsum reduce -> fp16 ---------------------------------------
__global__ void __launch_bounds__(256) colreduce_kernel() {
    const int b = blockIdx.x, d = threadIdx.x;
    float s = 0.f;
#pragma unroll
    for (int q = 0; q < 16; q++) s += g_spart[(b * 16 + q) * ID + d];
    g_s[b * ID + d] = __float2half_rn(s);
}

// ---------------- projection via mma: one block per capsule n -----------------
// smem: Wh [64][264]h @0 | Wt [256][72]h @33792 | Vs [64][264]h @70656
//       Os [64][68]f @104448 | Oh [64][72]h @121856   (total 131072 B)
template <int PHASE>
__global__ void __launch_bounds__(256) proj_kernel(const float* __restrict__ W,
                                                   float* __restrict__ out) {
    extern __shared__ char sm[];
    __half* Wh = (__half*)sm;
    __half* Wt = (__half*)(sm + 33792);
    __half* Vs = (__half*)(sm + 70656);
    float*  Os = (float*)(sm + 104448);
    __half* Oh = (__half*)(sm + 121856);

    const int n = blockIdx.x;
    const int t = threadIdx.x, w = t >> 5, l = t & 31;
    const int g = l >> 2, tig = l & 3;

    // load W_n rows 2p,2p+1; fill Wh (row) + Wt (transposed)
    {
        const int p = t >> 3, seg = t & 7;
        const float* src = W + ((size_t)n * DC + 2 * p) * ID + seg * 32;
        float4 q0[8], q1[8];
#pragma unroll
        for (int r = 0; r < 8; r++) q0[r] = ((const float4*)src)[r];
#pragma unroll
        for (int r = 0; r < 8; r++) q1[r] = ((const float4*)(src + ID))[r];
#pragma unroll
        for (int r = 0; r < 8; r++) {
            *(__half2*)&Wh[(2 * p) * 264 + seg * 32 + 4 * r]     = __floats2half2_rn(q0[r].x, q0[r].y);
            *(__half2*)&Wh[(2 * p) * 264 + seg * 32 + 4 * r + 2] = __floats2half2_rn(q0[r].z, q0[r].w);
            *(__half2*)&Wh[(2 * p + 1) * 264 + seg * 32 + 4 * r]     = __floats2half2_rn(q1[r].x, q1[r].y);
            *(__half2*)&Wh[(2 * p + 1) * 264 + seg * 32 + 4 * r + 2] = __floats2half2_rn(q1[r].z, q1[r].w);
            const int d = seg * 32 + 4 * r;
            *(__half2*)&Wt[(d + 0) * 72 + 2 * p] = __floats2half2_rn(q0[r].x, q1[r].x);
            *(__half2*)&Wt[(d + 1) * 72 + 2 * p] = __floats2half2_rn(q0[r].y, q1[r].y);
            *(__half2*)&Wt[(d + 2) * 72 + 2 * p] = __floats2half2_rn(q0[r].z, q1[r].z);
            *(__half2*)&Wt[(d + 3) * 72 + 2 * p] = __floats2half2_rn(q0[r].w, q1[r].w);
        }
    }

    // gather V: thread (b = t>>2, quarter c = t&3) covers 64 d
    {
        const int bb = t >> 2, c = t & 3;
        if (PHASE == 0) {
            const uint4* src = (const uint4*)(g_s + bb * ID + c * 64);
            uint4* dst = (uint4*)&Vs[bb * 264 + c * 64];
#pragma unroll
            for (int q = 0; q < 8; q++) dst[q] = src[q];
        } else {
            float acc[64];
#pragma unroll
            for (int k = 0; k < 64; k++) acc[k] = 0.f;
#pragma unroll
            for (int x = 0; x < 4; x++) {
                const float4* sp = (const float4*)(g_vpart + (((size_t)bb * 4 + x) * NC + n) * ID + c * 64);
#pragma unroll
                for (int r = 0; r < 16; r++) {
                    float4 v = sp[r];
                    acc[4 * r] += v.x; acc[4 * r + 1] += v.y;
                    acc[4 * r + 2] += v.z; acc[4 * r + 3] += v.w;
                }
            }
            uint4* dst = (uint4*)&Vs[bb * 264 + c * 64];
#pragma unroll
            for (int q = 0; q < 8; q++) {
                uint32_t w0 = h2u(__floats2half2_rn(acc[8 * q], acc[8 * q + 1]));
                uint32_t w1 = h2u(__floats2half2_rn(acc[8 * q + 2], acc[8 * q + 3]));
                uint32_t w2 = h2u(__floats2half2_rn(acc[8 * q + 4], acc[8 * q + 5]));
                uint32_t w3 = h2u(__floats2half2_rn(acc[8 * q + 6], acc[8 * q + 7]));
                dst[q] = make_uint4(w0, w1, w2, w3);
            }
        }
    }
    __syncthreads();

    // mma1: O[b,dc] = sum_d V[b,d] * W[dc,d]; warp: mt=w>>1 (16 b), h=w&1 (32 dc)
    const int mt = w >> 1, h = w & 1;
    {
        float f1[4][4];
#pragma unroll
        for (int j = 0; j < 4; j++)
#pragma unroll
            for (int r = 0; r < 4; r++) f1[j][r] = 0.f;
#pragma unroll
        for (int ks = 0; ks < 16; ks++) {
            uint32_t a[4];
            a[0] = *(const uint32_t*)&Vs[(16 * mt + g) * 264 + (8 * ks + tig) * 2];
            a[1] = *(const uint32_t*)&Vs[(16 * mt + 8 + g) * 264 + (8 * ks + tig) * 2];
            a[2] = *(const uint32_t*)&Vs[(16 * mt + g) * 264 + (8 * ks + tig + 4) * 2];
            a[3] = *(const uint32_t*)&Vs[(16 * mt + 8 + g) * 264 + (8 * ks + tig + 4) * 2];
#pragma unroll
            for (int j = 0; j < 4; j++) {
                const int dc0 = 32 * h + 8 * j;
                uint32_t bb[2];
                bb[0] = *(const uint32_t*)&Wh[(dc0 + g) * 264 + (8 * ks + tig) * 2];
                bb[1] = *(const uint32_t*)&Wh[(dc0 + g) * 264 + (8 * ks + tig + 4) * 2];
                mma_f16(f1[j], a, bb);
            }
        }
#pragma unroll
        for (int j = 0; j < 4; j++) {
            const int dc0 = 32 * h + 8 * j + 2 * tig;
            *(float2*)&Os[(16 * mt + g) * 68 + dc0] = make_float2(f1[j][0], f1[j][1]);
            *(float2*)&Os[(16 * mt + 8 + g) * 68 + dc0] = make_float2(f1[j][2], f1[j][3]);
        }
    }
    __syncthreads();

    // norms per b (quad-cooperative), then squash (PHASE 2) or normalize -> Oh
    {
        const int bb = t >> 2, c = t & 3;
        float p2 = 0.f;
#pragma unroll
        for (int j = 0; j < 16; j++) {
            float v = Os[bb * 68 + 16 * c + j];
            p2 += v * v;
        }
        p2 += __shfl_xor_sync(0xffffffffu, p2, 1);
        p2 += __shfl_xor_sync(0xffffffffu, p2, 2);
        if (PHASE == 2) {
            float sq = p2 + 1e-7f;
            float sc = sqrtf(sq) / (0.5f + sq);
#pragma unroll
            for (int j = 0; j < 16; j++)
                out[((size_t)bb * NC + n) * DC + 16 * c + j] = sc * Os[bb * 68 + 16 * c + j];
            return;
        }
        const float inv = 1.0f / fmaxf(sqrtf(p2), 1e-12f);
#pragma unroll
        for (int j = 0; j < 16; j++)
            Oh[bb * 72 + 16 * c + j] = __float2half_rn(Os[bb * 68 + 16 * c + j] * inv);
    }
    __syncthreads();

    // mma2: w~[b,d] = sum_dc Oh[b,dc] * Wt[d,dc]; warp: mt (16 b), h (128 d)
    {
        float f2[16][4];
#pragma unroll
        for (int j = 0; j < 16; j++)
#pragma unroll
            for (int r = 0; r < 4; r++) f2[j][r] = 0.f;
#pragma unroll
        for (int ks = 0; ks < 4; ks++) {
            uint32_t a[4];
            a[0] = *(const uint32_t*)&Oh[(16 * mt + g) * 72 + (8 * ks + tig) * 2];
            a[1] = *(const uint32_t*)&Oh[(16 * mt + 8 + g) * 72 + (8 * ks + tig) * 2];
            a[2] = *(const uint32_t*)&Oh[(16 * mt + g) * 72 + (8 * ks + tig + 4) * 2];
            a[3] = *(const uint32_t*)&Oh[(16 * mt + 8 + g) * 72 + (8 * ks + tig + 4) * 2];
#pragma unroll
            for (int j = 0; j < 16; j++) {
                const int dr = 128 * h + 8 * j + g;
                uint32_t bb[2];
                bb[0] = *(const uint32_t*)&Wt[dr * 72 + (8 * ks + tig) * 2];
                bb[1] = *(const uint32_t*)&Wt[dr * 72 + (8 * ks + tig + 4) * 2];
                mma_f16(f2[j], a, bb);
            }
        }
#pragma unroll
        for (int j = 0; j < 16; j++) {
            const int d0 = 128 * h + 8 * j + 2 * tig;
            const int b0 = 16 * mt + g;
            *(__half2*)&g_wtil[((size_t)b0 * NC + n) * ID + d0] =
                __floats2half2_rn(f2[j][0], f2[j][1]);
            *(__half2*)&g_wtil[((size_t)(b0 + 8) * NC + n) * ID + d0] =
                __floats2half2_rn(f2[j][2], f2[j][3]);
        }
    }
}

// ---------------- fused routing: 4 chunks/block, V in registers --------------
// smem: uh [64][264]h @0 | ut [256][66]h @33792 | wsh [32][264]h @67584
//       csh [32][72]h @84480 | Lsh [64][34]f @89088   (total 97792 B)
__global__ void __launch_bounds__(256, 2) fused_kernel() {
    extern __shared__ char smem[];
    __half* uh = (__half*)smem;
    __half* ut = (__half*)(smem + 33792);
    __half* wsh = (__half*)(smem + 67584);
    __half* csh = (__half*)(smem + 84480);
    float* Lsh = (float*)(smem + 89088);

    const int b = blockIdx.y;
    const int t = threadIdx.x, w = t >> 5, l = t & 31;
    const int g = l >> 2, tig = l & 3;

    // load w~
    {
        const int n = t >> 3, seg = t & 7;
        const uint4* wp = (const uint4*)(g_wtil + ((size_t)b * NC + n) * ID + seg * 32);
        uint4* ws = (uint4*)&wsh[n * 264 + seg * 32];
        ws[0] = wp[0]; ws[1] = wp[1]; ws[2] = wp[2]; ws[3] = wp[3];
    }

    float vfr[2][4][4];
#pragma unroll
    for (int s = 0; s < 2; s++)
#pragma unroll
        for (int nt = 0; nt < 4; nt++)
#pragma unroll
            for (int r = 0; r < 4; r++) vfr[s][nt][r] = 0.f;

    for (int grp = 0; grp < 4; grp++) {
        const int i0 = (blockIdx.x * 4 + grp) * 64;

        // copy uh tile (row-major, no conversion)
        {
            const int i = t >> 2, c = t & 3;
            const uint4* src = (const uint4*)(g_uh + ((size_t)b * IN + i0 + i) * ID + c * 64);
            uint4* dst = (uint4*)&uh[i * 264 + c * 64];
#pragma unroll
            for (int q = 0; q < 8; q++) dst[q] = src[q];
        }
        // copy ut tile with column swizzle (rot = 4*(d>>5))
        {
            const int d = t;
            const uint4* src = (const uint4*)(g_ut + ((size_t)b * ID + d) * IN + i0);
            uint32_t buf[32];
#pragma unroll
            for (int q = 0; q < 8; q++) {
                uint4 v = src[q];
                buf[4 * q] = v.x; buf[4 * q + 1] = v.y; buf[4 * q + 2] = v.z; buf[4 * q + 3] = v.w;
            }
            const int rot = 4 * (d >> 5);
#pragma unroll
            for (int q = 0; q < 32; q++)
                ((uint32_t*)&ut[d * 66])[(q + rot) & 31] = buf[q];
        }
        __syncthreads();

        // logits mma: warp w: mt = w>>1 (16 i), hh = w&1 (16 n)
        {
            const int lmt = w >> 1, hh = w & 1;
            float f[2][4];
#pragma unroll
            for (int nt = 0; nt < 2; nt++)
#pragma unroll
                for (int r = 0; r < 4; r++) f[nt][r] = 0.f;
#pragma unroll
            for (int ks = 0; ks < 16; ks++) {
                uint32_t a[4];
                a[0] = *(const uint32_t*)&uh[(16 * lmt + g) * 264 + (8 * ks + tig) * 2];
                a[1] = *(const uint32_t*)&uh[(16 * lmt + 8 + g) * 264 + (8 * ks + tig) * 2];
                a[2] = *(const uint32_t*)&uh[(16 * lmt + g) * 264 + (8 * ks + tig + 4) * 2];
                a[3] = *(const uint32_t*)&uh[(16 * lmt + 8 + g) * 264 + (8 * ks + tig + 4) * 2];
#pragma unroll
                for (int nt = 0; nt < 2; nt++) {
                    const int n0 = hh * 16 + nt * 8;
                    uint32_t bb[2];
                    bb[0] = *(const uint32_t*)&wsh[(n0 + g) * 264 + (8 * ks + tig) * 2];
                    bb[1] = *(const uint32_t*)&wsh[(n0 + g) * 264 + (8 * ks + tig + 4) * 2];
                    mma_f16(f[nt], a, bb);
                }
            }
#pragma unroll
            for (int nt = 0; nt < 2; nt++) {
                const int n0 = hh * 16 + nt * 8 + 2 * tig;
                *(float2*)&Lsh[(16 * lmt + g) * 34 + n0] = make_float2(f[nt][0], f[nt][1]);
                *(float2*)&Lsh[(16 * lmt + 8 + g) * 34 + n0] = make_float2(f[nt][2], f[nt][3]);
            }
        }
        __syncthreads();

        // softmax over n (lane = n); warp w: i rows 8w..8w+7
#pragma unroll
        for (int r8 = 0; r8 < 8; r8++) {
            const int r = w * 8 + r8;
            const float val = Lsh[r * 34 + l];
            float mx = val;
#pragma unroll
            for (int off = 16; off; off >>= 1)
                mx = fmaxf(mx, __shfl_xor_sync(0xffffffffu, mx, off));
            const float e = __expf(val - mx);
            float s = e;
#pragma unroll
            for (int off = 16; off; off >>= 1) s += __shfl_xor_sync(0xffffffffu, s, off);
            csh[l * 72 + r] = __float2half_rn(e / s);
        }
        __syncthreads();

        // accumulation mma: V[d,n] += sum_i ut[d,i] * c[n,i]
        {
            const int sw = 4 * (w & 7);
#pragma unroll
            for (int ks = 0; ks < 4; ks++) {
                const int kw0 = 8 * ks + tig, kw1 = kw0 + 4;
                uint32_t a[2][4];
#pragma unroll
                for (int s = 0; s < 2; s++) {
                    const int dr0 = 32 * w + 16 * s + g;
                    a[s][0] = *(const uint32_t*)&ut[dr0 * 66 + (((kw0 + sw) & 31) << 1)];
                    a[s][1] = *(const uint32_t*)&ut[(dr0 + 8) * 66 + (((kw0 + sw) & 31) << 1)];
                    a[s][2] = *(const uint32_t*)&ut[dr0 * 66 + (((kw1 + sw) & 31) << 1)];
                    a[s][3] = *(const uint32_t*)&ut[(dr0 + 8) * 66 + (((kw1 + sw) & 31) << 1)];
                }
#pragma unroll
                for (int nt = 0; nt < 4; nt++) {
                    uint32_t bb[2];
                    bb[0] = *(const uint32_t*)&csh[(8 * nt + g) * 72 + (8 * ks + tig) * 2];
                    bb[1] = *(const uint32_t*)&csh[(8 * nt + g) * 72 + (8 * ks + tig + 4) * 2];
                    mma_f16(vfr[0][nt], a[0], bb);
                    mma_f16(vfr[1][nt], a[1], bb);
                }
            }
        }
        __syncthreads();  // protect smem for next group
    }

    // store V partials for this i-group of 256
    float* vp = g_vpart + (((size_t)b * 4 + blockIdx.x) * NC) * ID;
#pragma unroll
    for (int s = 0; s < 2; s++) {
        const int d0 = 32 * w + 16 * s + g;
#pragma unroll
        for (int nt = 0; nt < 4; nt++) {
            const int n0 = 8 * nt + 2 * tig;
            vp[(size_t)n0 * ID + d0] = vfr[s][nt][0];
            vp[(size_t)(n0 + 1) * ID + d0] = vfr[s][nt][1];
            vp[(size_t)n0 * ID + d0 + 8] = vfr[s][nt][2];
            vp[(size_t)(n0 + 1) * ID + d0 + 8] = vfr[s][nt][3];
        }
    }
}

// ---------------- launch ------------------------------------------------------
extern "C" void kernel_launch(void* const* d_in, const int* in_sizes, int n_in,
                              void* d_out, int out_size) {
    (void)in_sizes; (void)n_in; (void)out_size;
    const float* u = (const float*)d_in[0];   // [64, 1024, 256] fp32
    const float* W = (const float*)d_in[1];   // [2048, 256] fp32
    float* out = (float*)d_out;               // [64, 32, 64] fp32

    const int pbytes = 131072;  // proj smem
    const int fbytes = 97792;   // fused smem
    static int attr_done = 0;
    if (!attr_done) {
        cudaFuncSetAttribute(proj_kernel<0>, cudaFuncAttributeMaxDynamicSharedMemorySize, pbytes);
        cudaFuncSetAttribute(proj_kernel<1>, cudaFuncAttributeMaxDynamicSharedMemorySize, pbytes);
        cudaFuncSetAttribute(proj_kernel<2>, cudaFuncAttributeMaxDynamicSharedMemorySize, pbytes);
        cudaFuncSetAttribute(fused_kernel, cudaFuncAttributeMaxDynamicSharedMemorySize, fbytes);
        attr_done = 1;
    }

    prep_kernel<<<dim3(16, B), 256>>>(u);               // u -> fp16 x2 + partials
    colreduce_kernel<<<B, 256>>>();                     // colsum -> fp16
    proj_kernel<0><<<NC, 256, pbytes>>>(W, out);        // o0 -> w~0
    fused_kernel<<<dim3(4, B), 256, fbytes>>>();        // iter 1 -> v1
    proj_kernel<1><<<NC, 256, pbytes>>>(W, out);        // o1 -> w~1
    fused_kernel<<<dim3(4, B), 256, fbytes>>>();        // iter 2 -> v2
    proj_kernel<2><<<NC, 256, pbytes>>>(W, out);        // squash -> out
}

// round 12
// speedup vs baseline: 1.3200x; 1.2502x over previous
#include <cuda_runtime.h>
#include <cuda_fp16.h>
#include <cstdint>

#define B 64
#define IN 1024
#define ID 256
#define NC 32
#define DC 64

// ---------------- static scratch ---------------------------------------------
__device__ __half g_uh[(size_t)B * IN * ID];          // u fp16 [b,i,d]   32 MB
__device__ float  g_spart[B * 16 * ID];               // colsum partials
__device__ __half g_s[B * ID];                        // colsum fp16
__device__ __half g_wtil[B * NC * ID];                // w~ fp16
__device__ float  g_vpart[(size_t)B * 4 * NC * ID];   // v partials  8 MB

// ---------------- helpers ----------------------------------------------------
__device__ __forceinline__ void mma_f16(float* d, const uint32_t* a, const uint32_t* b) {
    asm volatile(
        "mma.sync.aligned.m16n8k16.row.col.f32.f16.f16.f32 "
        "{%0,%1,%2,%3}, {%4,%5,%6,%7}, {%8,%9}, {%0,%1,%2,%3};"
        : "+f"(d[0]), "+f"(d[1]), "+f"(d[2]), "+f"(d[3])
        : "r"(a[0]), "r"(a[1]), "r"(a[2]), "r"(a[3]), "r"(b[0]), "r"(b[1]));
}
__device__ __forceinline__ uint32_t h2u(__half2 h) { return *reinterpret_cast<uint32_t*>(&h); }
__device__ __forceinline__ uint32_t s2u(const void* p) {
    return (uint32_t)__cvta_generic_to_shared(p);
}
__device__ __forceinline__ void ldsm4(uint32_t* r, uint32_t a) {
    asm volatile("ldmatrix.sync.aligned.m8n8.x4.shared.b16 {%0,%1,%2,%3}, [%4];"
                 : "=r"(r[0]), "=r"(r[1]), "=r"(r[2]), "=r"(r[3]) : "r"(a));
}
__device__ __forceinline__ void ldsm4t(uint32_t* r, uint32_t a) {
    asm volatile("ldmatrix.sync.aligned.m8n8.x4.trans.shared.b16 {%0,%1,%2,%3}, [%4];"
                 : "=r"(r[0]), "=r"(r[1]), "=r"(r[2]), "=r"(r[3]) : "r"(a));
}

// ---------------- prep: u -> fp16 row-major + colsum partials ----------------
__global__ void __launch_bounds__(256, 2) prep_kernel(const float* __restrict__ u) {
    __shared__ float cs_sh[32][256];                 // 32 KB
    const int ib = blockIdx.x, b = blockIdx.y;
    const int t = threadIdx.x;
    const int p = t >> 3, seg = t & 7;               // i-pair p, d-group seg
    const int i0 = ib * 64;

    const float* src = u + ((size_t)b * IN + i0 + 2 * p) * ID + seg * 32;
    float4 q0[8], q1[8];
#pragma unroll
    for (int r = 0; r < 8; r++) q0[r] = ((const float4*)src)[r];
#pragma unroll
    for (int r = 0; r < 8; r++) q1[r] = ((const float4*)(src + ID))[r];

    // g_uh rows 2p, 2p+1
    {
        uint32_t ha[16], hb[16];
#pragma unroll
        for (int r = 0; r < 8; r++) {
            ha[2 * r]     = h2u(__floats2half2_rn(q0[r].x, q0[r].y));
            ha[2 * r + 1] = h2u(__floats2half2_rn(q0[r].z, q0[r].w));
            hb[2 * r]     = h2u(__floats2half2_rn(q1[r].x, q1[r].y));
            hb[2 * r + 1] = h2u(__floats2half2_rn(q1[r].z, q1[r].w));
        }
        uint4* d0 = (uint4*)(g_uh + ((size_t)b * IN + i0 + 2 * p) * ID + seg * 32);
        uint4* d1 = (uint4*)(g_uh + ((size_t)b * IN + i0 + 2 * p + 1) * ID + seg * 32);
#pragma unroll
        for (int q = 0; q < 4; q++) {
            d0[q] = make_uint4(ha[4 * q], ha[4 * q + 1], ha[4 * q + 2], ha[4 * q + 3]);
            d1[q] = make_uint4(hb[4 * q], hb[4 * q + 1], hb[4 * q + 2], hb[4 * q + 3]);
        }
    }

    // per-thread partial colsum (2 rows x 32 d)
#pragma unroll
    for (int r = 0; r < 8; r++) {
        float4 s4 = make_float4(q0[r].x + q1[r].x, q0[r].y + q1[r].y,
                                q0[r].z + q1[r].z, q0[r].w + q1[r].w);
        *(float4*)&cs_sh[p][seg * 32 + 4 * r] = s4;
    }
    __syncthreads();

    {
        const int d = t;
        float cs = 0.f;
#pragma unroll
        for (int q = 0; q < 32; q++) cs += cs_sh[q][d];
        g_spart[(b * 16 + ib) * ID + d] = cs;
    }
}

// ---------------- colsum reduce -> fp16 ---------------------------------------
__global__ void __launch_bounds__(256) colreduce_kernel() {
    const int b = blockIdx.x, d = threadIdx.x;
    float s = 0.f;
#pragma unroll
    for (int q = 0; q < 16; q++) s += g_spart[(b * 16 + q) * ID + d];
    g_s[b * ID + d] = __float2half_rn(s);
}

// ---------------- projection via mma: one block per capsule n -----------------
// smem: Wh [64][264]h @0 | Wt [256][72]h @33792 | Vs [64][264]h @70656
//       Os [64][68]f @104448 | Oh [64][72]h @121856   (total 131072 B)
template <int PHASE>
__global__ void __launch_bounds__(256) proj_kernel(const float* __restrict__ W,
                                                   float* __restrict__ out) {
    extern __shared__ char sm[];
    __half* Wh = (__half*)sm;
    __half* Wt = (__half*)(sm + 33792);
    __half* Vs = (__half*)(sm + 70656);
    float*  Os = (float*)(sm + 104448);
    __half* Oh = (__half*)(sm + 121856);

    const int n = blockIdx.x;
    const int t = threadIdx.x, w = t >> 5, l = t & 31;
    const int g = l >> 2, tig = l & 3;

    // load W_n rows 2p,2p+1; fill Wh (row) + Wt (transposed)
    {
        const int p = t >> 3, seg = t & 7;
        const float* src = W + ((size_t)n * DC + 2 * p) * ID + seg * 32;
        float4 q0[8], q1[8];
#pragma unroll
        for (int r = 0; r < 8; r++) q0[r] = ((const float4*)src)[r];
#pragma unroll
        for (int r = 0; r < 8; r++) q1[r] = ((const float4*)(src + ID))[r];
#pragma unroll
        for (int r = 0; r < 8; r++) {
            *(__half2*)&Wh[(2 * p) * 264 + seg * 32 + 4 * r]     = __floats2half2_rn(q0[r].x, q0[r].y);
            *(__half2*)&Wh[(2 * p) * 264 + seg * 32 + 4 * r + 2] = __floats2half2_rn(q0[r].z, q0[r].w);
            *(__half2*)&Wh[(2 * p + 1) * 264 + seg * 32 + 4 * r]     = __floats2half2_rn(q1[r].x, q1[r].y);
            *(__half2*)&Wh[(2 * p + 1) * 264 + seg * 32 + 4 * r + 2] = __floats2half2_rn(q1[r].z, q1[r].w);
            const int d = seg * 32 + 4 * r;
            *(__half2*)&Wt[(d + 0) * 72 + 2 * p] = __floats2half2_rn(q0[r].x, q1[r].x);
            *(__half2*)&Wt[(d + 1) * 72 + 2 * p] = __floats2half2_rn(q0[r].y, q1[r].y);
            *(__half2*)&Wt[(d + 2) * 72 + 2 * p] = __floats2half2_rn(q0[r].z, q1[r].z);
            *(__half2*)&Wt[(d + 3) * 72 + 2 * p] = __floats2half2_rn(q0[r].w, q1[r].w);
        }
    }

    // gather V: thread (b = t>>2, quarter c = t&3) covers 64 d
    {
        const int bb = t >> 2, c = t & 3;
        if (PHASE == 0) {
            const uint4* src = (const uint4*)(g_s + bb * ID + c * 64);
            uint4* dst = (uint4*)&Vs[bb * 264 + c * 64];
#pragma unroll
            for (int q = 0; q < 8; q++) dst[q] = src[q];
        } else {
            float acc[64];
#pragma unroll
            for (int k = 0; k < 64; k++) acc[k] = 0.f;
#pragma unroll
            for (int x = 0; x < 4; x++) {
                const float4* sp = (const float4*)(g_vpart + (((size_t)bb * 4 + x) * NC + n) * ID + c * 64);
#pragma unroll
                for (int r = 0; r < 16; r++) {
                    float4 v = sp[r];
                    acc[4 * r] += v.x; acc[4 * r + 1] += v.y;
                    acc[4 * r + 2] += v.z; acc[4 * r + 3] += v.w;
                }
            }
            uint4* dst = (uint4*)&Vs[bb * 264 + c * 64];
#pragma unroll
            for (int q = 0; q < 8; q++) {
                uint32_t w0 = h2u(__floats2half2_rn(acc[8 * q], acc[8 * q + 1]));
                uint32_t w1 = h2u(__floats2half2_rn(acc[8 * q + 2], acc[8 * q + 3]));
                uint32_t w2 = h2u(__floats2half2_rn(acc[8 * q + 4], acc[8 * q + 5]));
                uint32_t w3 = h2u(__floats2half2_rn(acc[8 * q + 6], acc[8 * q + 7]));
                dst[q] = make_uint4(w0, w1, w2, w3);
            }
        }
    }
    __syncthreads();

    // mma1: O[b,dc] = sum_d V[b,d] * W[dc,d]; warp: mt=w>>1 (16 b), h=w&1 (32 dc)
    const int mt = w >> 1, h = w & 1;
    {
        float f1[4][4];
#pragma unroll
        for (int j = 0; j < 4; j++)
#pragma unroll
            for (int r = 0; r < 4; r++) f1[j][r] = 0.f;
#pragma unroll
        for (int ks = 0; ks < 16; ks++) {
            uint32_t a[4];
            a[0] = *(const uint32_t*)&Vs[(16 * mt + g) * 264 + (8 * ks + tig) * 2];
            a[1] = *(const uint32_t*)&Vs[(16 * mt + 8 + g) * 264 + (8 * ks + tig) * 2];
            a[2] = *(const uint32_t*)&Vs[(16 * mt + g) * 264 + (8 * ks + tig + 4) * 2];
            a[3] = *(const uint32_t*)&Vs[(16 * mt + 8 + g) * 264 + (8 * ks + tig + 4) * 2];
#pragma unroll
            for (int j = 0; j < 4; j++) {
                const int dc0 = 32 * h + 8 * j;
                uint32_t bb[2];
                bb[0] = *(const uint32_t*)&Wh[(dc0 + g) * 264 + (8 * ks + tig) * 2];
                bb[1] = *(const uint32_t*)&Wh[(dc0 + g) * 264 + (8 * ks + tig + 4) * 2];
                mma_f16(f1[j], a, bb);
            }
        }
#pragma unroll
        for (int j = 0; j < 4; j++) {
            const int dc0 = 32 * h + 8 * j + 2 * tig;
            *(float2*)&Os[(16 * mt + g) * 68 + dc0] = make_float2(f1[j][0], f1[j][1]);
            *(float2*)&Os[(16 * mt + 8 + g) * 68 + dc0] = make_float2(f1[j][2], f1[j][3]);
        }
    }
    __syncthreads();

    // norms per b (quad-cooperative), then squash (PHASE 2) or normalize -> Oh
    {
        const int bb = t >> 2, c = t & 3;
        float p2 = 0.f;
#pragma unroll
        for (int j = 0; j < 16; j++) {
            float v = Os[bb * 68 + 16 * c + j];
            p2 += v * v;
        }
        p2 += __shfl_xor_sync(0xffffffffu, p2, 1);
        p2 += __shfl_xor_sync(0xffffffffu, p2, 2);
        if (PHASE == 2) {
            float sq = p2 + 1e-7f;
            float sc = sqrtf(sq) / (0.5f + sq);
#pragma unroll
            for (int j = 0; j < 16; j++)
                out[((size_t)bb * NC + n) * DC + 16 * c + j] = sc * Os[bb * 68 + 16 * c + j];
            return;
        }
        const float inv = 1.0f / fmaxf(sqrtf(p2), 1e-12f);
#pragma unroll
        for (int j = 0; j < 16; j++)
            Oh[bb * 72 + 16 * c + j] = __float2half_rn(Os[bb * 68 + 16 * c + j] * inv);
    }
    __syncthreads();

    // mma2: w~[b,d] = sum_dc Oh[b,dc] * Wt[d,dc]; warp: mt (16 b), h (128 d)
    {
        float f2[16][4];
#pragma unroll
        for (int j = 0; j < 16; j++)
#pragma unroll
            for (int r = 0; r < 4; r++) f2[j][r] = 0.f;
#pragma unroll
        for (int ks = 0; ks < 4; ks++) {
            uint32_t a[4];
            a[0] = *(const uint32_t*)&Oh[(16 * mt + g) * 72 + (8 * ks + tig) * 2];
            a[1] = *(const uint32_t*)&Oh[(16 * mt + 8 + g) * 72 + (8 * ks + tig) * 2];
            a[2] = *(const uint32_t*)&Oh[(16 * mt + g) * 72 + (8 * ks + tig + 4) * 2];
            a[3] = *(const uint32_t*)&Oh[(16 * mt + 8 + g) * 72 + (8 * ks + tig + 4) * 2];
#pragma unroll
            for (int j = 0; j < 16; j++) {
                const int dr = 128 * h + 8 * j + g;
                uint32_t bb[2];
                bb[0] = *(const uint32_t*)&Wt[dr * 72 + (8 * ks + tig) * 2];
                bb[1] = *(const uint32_t*)&Wt[dr * 72 + (8 * ks + tig + 4) * 2];
                mma_f16(f2[j], a, bb);
            }
        }
#pragma unroll
        for (int j = 0; j < 16; j++) {
            const int d0 = 128 * h + 8 * j + 2 * tig;
            const int b0 = 16 * mt + g;
            *(__half2*)&g_wtil[((size_t)b0 * NC + n) * ID + d0] =
                __floats2half2_rn(f2[j][0], f2[j][1]);
            *(__half2*)&g_wtil[((size_t)(b0 + 8) * NC + n) * ID + d0] =
                __floats2half2_rn(f2[j][2], f2[j][3]);
        }
    }
}

// ---------------- fused routing: ldmatrix + trans-ldmatrix, no ut copy -------
// smem: uh [64][264]h @0 (33792) | wsh [32][264]h @33792 (16896)
//       csh [32][72]h @50688 (4608) | Lsh [64][34]f @55296 (8704) -> 64000 B
__global__ void __launch_bounds__(256, 2) fused_kernel() {
    extern __shared__ char smem[];
    __half* uh = (__half*)smem;
    __half* wsh = (__half*)(smem + 33792);
    __half* csh = (__half*)(smem + 50688);
    float* Lsh = (float*)(smem + 55296);

    const int b = blockIdx.y;
    const int t = threadIdx.x, w = t >> 5, l = t & 31;
    const int g = l >> 2, tig = l & 3;

    // load w~
    {
        const int n = t >> 3, seg = t & 7;
        const uint4* wp = (const uint4*)(g_wtil + ((size_t)b * NC + n) * ID + seg * 32);
        uint4* ws = (uint4*)&wsh[n * 264 + seg * 32];
        ws[0] = wp[0]; ws[1] = wp[1]; ws[2] = wp[2]; ws[3] = wp[3];
    }

    // ldmatrix per-lane base addresses
    const int lA = l & 15;                 // A row offset within tile (x4 pattern)
    const int lAc = (l >> 4) * 16;         // A col byte offset (8 halves)
    const int lB = (l & 7) + 8 * (l >> 4); // B row offset within tile
    const int lBc = ((l >> 3) & 1) * 16;   // B col byte offset

    const uint32_t uhA = s2u(uh) + ((16 * (w >> 1) + lA) * 264) * 2 + lAc;  // logits A
    const uint32_t wB  = s2u(wsh) + (((w & 1) * 16 + lB) * 264) * 2 + lBc;  // logits B
    const uint32_t uhT = s2u(uh) + (lB * 264 + 32 * w) * 2 + lBc;           // accum A (trans)
    const uint32_t cB  = s2u(csh) + (lB * 72) * 2 + lBc;                    // accum B

    float vfr[2][4][4];
#pragma unroll
    for (int s = 0; s < 2; s++)
#pragma unroll
        for (int nt = 0; nt < 4; nt++)
#pragma unroll
            for (int r = 0; r < 4; r++) vfr[s][nt][r] = 0.f;

    for (int grp = 0; grp < 4; grp++) {
        const int i0 = (blockIdx.x * 4 + grp) * 64;

        // copy uh tile (row-major fp16, uint4)
        {
            const int i = t >> 2, c = t & 3;
            const uint4* src = (const uint4*)(g_uh + ((size_t)b * IN + i0 + i) * ID + c * 64);
            uint4* dst = (uint4*)&uh[i * 264 + c * 64];
#pragma unroll
            for (int q = 0; q < 8; q++) dst[q] = src[q];
        }
        __syncthreads();

        // logits mma: warp w: i rows 16*(w>>1).., n half (w&1)*16
        {
            float f[2][4];
#pragma unroll
            for (int nt = 0; nt < 2; nt++)
#pragma unroll
                for (int r = 0; r < 4; r++) f[nt][r] = 0.f;
#pragma unroll
            for (int ks = 0; ks < 16; ks++) {
                uint32_t a[4], bb[4];
                ldsm4(a, uhA + ks * 32);
                ldsm4(bb, wB + ks * 32);
                mma_f16(f[0], a, bb);
                mma_f16(f[1], a, bb + 2);
            }
            const int lmt = w >> 1, hh = w & 1;
#pragma unroll
            for (int nt = 0; nt < 2; nt++) {
                const int n0 = hh * 16 + nt * 8 + 2 * tig;
                *(float2*)&Lsh[(16 * lmt + g) * 34 + n0] = make_float2(f[nt][0], f[nt][1]);
                *(float2*)&Lsh[(16 * lmt + 8 + g) * 34 + n0] = make_float2(f[nt][2], f[nt][3]);
            }
        }
        __syncthreads();

        // softmax over n (lane = n); warp w: i rows 8w..8w+7
#pragma unroll
        for (int r8 = 0; r8 < 8; r8++) {
            const int r = w * 8 + r8;
            const float val = Lsh[r * 34 + l];
            float mx = val;
#pragma unroll
            for (int off = 16; off; off >>= 1)
                mx = fmaxf(mx, __shfl_xor_sync(0xffffffffu, mx, off));
            const float e = __expf(val - mx);
            float s = e;
#pragma unroll
            for (int off = 16; off; off >>= 1) s += __shfl_xor_sync(0xffffffffu, s, off);
            csh[l * 72 + r] = __float2half_rn(e / s);
        }
        __syncthreads();

        // accumulation mma: V[d,n] += sum_i uh^T[d,i] * c[n,i]  (trans ldmatrix)
        {
#pragma unroll
            for (int ks = 0; ks < 4; ks++) {
                uint32_t a0[4], a1[4], c0[4], c1[4];
                ldsm4t(a0, uhT + ks * 8448);            // d tile 32w..+15
                ldsm4t(a1, uhT + 32 + ks * 8448);       // d tile 32w+16..+31
                ldsm4(c0, cB + ks * 32);                // n tiles 0,1
                ldsm4(c1, cB + 2304 + ks * 32);         // n tiles 2,3
                mma_f16(vfr[0][0], a0, c0); mma_f16(vfr[0][1], a0, c0 + 2);
                mma_f16(vfr[0][2], a0, c1); mma_f16(vfr[0][3], a0, c1 + 2);
                mma_f16(vfr[1][0], a1, c0); mma_f16(vfr[1][1], a1, c0 + 2);
                mma_f16(vfr[1][2], a1, c1); mma_f16(vfr[1][3], a1, c1 + 2);
            }
        }
        __syncthreads();  // protect smem for next group
    }

    // store V partials for this i-group of 256
    float* vp = g_vpart + (((size_t)b * 4 + blockIdx.x) * NC) * ID;
#pragma unroll
    for (int s = 0; s < 2; s++) {
        const int d0 = 32 * w + 16 * s + g;
#pragma unroll
        for (int nt = 0; nt < 4; nt++) {
            const int n0 = 8 * nt + 2 * tig;
            vp[(size_t)n0 * ID + d0] = vfr[s][nt][0];
            vp[(size_t)(n0 + 1) * ID + d0] = vfr[s][nt][1];
            vp[(size_t)n0 * ID + d0 + 8] = vfr[s][nt][2];
            vp[(size_t)(n0 + 1) * ID + d0 + 8] = vfr[s][nt][3];
        }
    }
}

// ---------------- launch ------------------------------------------------------
extern "C" void kernel_launch(void* const* d_in, const int* in_sizes, int n_in,
                              void* d_out, int out_size) {
    (void)in_sizes; (void)n_in; (void)out_size;
    const float* u = (const float*)d_in[0];   // [64, 1024, 256] fp32
    const float* W = (const float*)d_in[1];   // [2048, 256] fp32
    float* out = (float*)d_out;               // [64, 32, 64] fp32

    const int pbytes = 131072;  // proj smem
    const int fbytes = 64000;   // fused smem
    static int attr_done = 0;
    if (!attr_done) {
        cudaFuncSetAttribute(proj_kernel<0>, cudaFuncAttributeMaxDynamicSharedMemorySize, pbytes);
        cudaFuncSetAttribute(proj_kernel<1>, cudaFuncAttributeMaxDynamicSharedMemorySize, pbytes);
        cudaFuncSetAttribute(proj_kernel<2>, cudaFuncAttributeMaxDynamicSharedMemorySize, pbytes);
        cudaFuncSetAttribute(fused_kernel, cudaFuncAttributeMaxDynamicSharedMemorySize, fbytes);
        attr_done = 1;
    }

    prep_kernel<<<dim3(16, B), 256>>>(u);               // u -> fp16 + partials
    colreduce_kernel<<<B, 256>>>();                     // colsum -> fp16
    proj_kernel<0><<<NC, 256, pbytes>>>(W, out);        // o0 -> w~0
    fused_kernel<<<dim3(4, B), 256, fbytes>>>();        // iter 1 -> v1
    proj_kernel<1><<<NC, 256, pbytes>>>(W, out);        // o1 -> w~1
    fused_kernel<<<dim3(4, B), 256, fbytes>>>();        // iter 2 -> v2
    proj_kernel<2><<<NC, 256, pbytes>>>(W, out);        // squash -> out
}

// round 13
// speedup vs baseline: 1.3878x; 1.0513x over previous
#include <cuda_runtime.h>
#include <cuda_fp16.h>
#include <cstdint>

#define B 64
#define IN 1024
#define ID 256
#define NC 32
#define DC 64

// ---------------- static scratch ---------------------------------------------
__device__ __half g_uh[(size_t)B * IN * ID];           // u fp16 [b,i,d]   32 MB
__device__ float  g_spart[B * 16 * ID];                // colsum partials
__device__ __half g_s[B * ID];                         // colsum fp16
__device__ __half g_wtil[B * NC * ID];                 // w~ fp16
__device__ float  g_vpart[(size_t)B * 16 * NC * ID];   // v partials  32 MB
__device__ __half g_Whg[NC * DC * ID];                 // W fp16 row-major
__device__ __half g_Wtg[NC * ID * DC];                 // W fp16 transposed

// ---------------- helpers ----------------------------------------------------
__device__ __forceinline__ void mma_f16(float* d, const uint32_t* a, const uint32_t* b) {
    asm volatile(
        "mma.sync.aligned.m16n8k16.row.col.f32.f16.f16.f32 "
        "{%0,%1,%2,%3}, {%4,%5,%6,%7}, {%8,%9}, {%0,%1,%2,%3};"
        : "+f"(d[0]), "+f"(d[1]), "+f"(d[2]), "+f"(d[3])
        : "r"(a[0]), "r"(a[1]), "r"(a[2]), "r"(a[3]), "r"(b[0]), "r"(b[1]));
}
__device__ __forceinline__ uint32_t h2u(__half2 h) { return *reinterpret_cast<uint32_t*>(&h); }
__device__ __forceinline__ uint32_t s2u(const void* p) {
    return (uint32_t)__cvta_generic_to_shared(p);
}
__device__ __forceinline__ void ldsm4(uint32_t* r, uint32_t a) {
    asm volatile("ldmatrix.sync.aligned.m8n8.x4.shared.b16 {%0,%1,%2,%3}, [%4];"
                 : "=r"(r[0]), "=r"(r[1]), "=r"(r[2]), "=r"(r[3]) : "r"(a));
}
__device__ __forceinline__ void ldsm4t(uint32_t* r, uint32_t a) {
    asm volatile("ldmatrix.sync.aligned.m8n8.x4.trans.shared.b16 {%0,%1,%2,%3}, [%4];"
                 : "=r"(r[0]), "=r"(r[1]), "=r"(r[2]), "=r"(r[3]) : "r"(a));
}

// ---------------- prep: u -> fp16 row-major + colsum partials ----------------
__global__ void __launch_bounds__(256, 2) prep_kernel(const float* __restrict__ u) {
    __shared__ float cs_sh[32][256];
    const int ib = blockIdx.x, b = blockIdx.y;
    const int t = threadIdx.x;
    const int p = t >> 3, seg = t & 7;
    const int i0 = ib * 64;

    const float* src = u + ((size_t)b * IN + i0 + 2 * p) * ID + seg * 32;
    float4 q0[8], q1[8];
#pragma unroll
    for (int r = 0; r < 8; r++) q0[r] = ((const float4*)src)[r];
#pragma unroll
    for (int r = 0; r < 8; r++) q1[r] = ((const float4*)(src + ID))[r];

    {
        uint32_t ha[16], hb[16];
#pragma unroll
        for (int r = 0; r < 8; r++) {
            ha[2 * r]     = h2u(__floats2half2_rn(q0[r].x, q0[r].y));
            ha[2 * r + 1] = h2u(__floats2half2_rn(q0[r].z, q0[r].w));
            hb[2 * r]     = h2u(__floats2half2_rn(q1[r].x, q1[r].y));
            hb[2 * r + 1] = h2u(__floats2half2_rn(q1[r].z, q1[r].w));
        }
        uint4* d0 = (uint4*)(g_uh + ((size_t)b * IN + i0 + 2 * p) * ID + seg * 32);
        uint4* d1 = (uint4*)(g_uh + ((size_t)b * IN + i0 + 2 * p + 1) * ID + seg * 32);
#pragma unroll
        for (int q = 0; q < 4; q++) {
            d0[q] = make_uint4(ha[4 * q], ha[4 * q + 1], ha[4 * q + 2], ha[4 * q + 3]);
            d1[q] = make_uint4(hb[4 * q], hb[4 * q + 1], hb[4 * q + 2], hb[4 * q + 3]);
        }
    }

#pragma unroll
    for (int r = 0; r < 8; r++) {
        float4 s4 = make_float4(q0[r].x + q1[r].x, q0[r].y + q1[r].y,
                                q0[r].z + q1[r].z, q0[r].w + q1[r].w);
        *(float4*)&cs_sh[p][seg * 32 + 4 * r] = s4;
    }
    __syncthreads();
    {
        const int d = t;
        float cs = 0.f;
#pragma unroll
        for (int q = 0; q < 32; q++) cs += cs_sh[q][d];
        g_spart[(b * 16 + ib) * ID + d] = cs;
    }
}

// ---------------- colsum reduce -> fp16 ---------------------------------------
__global__ void __launch_bounds__(256) colreduce_kernel() {
    const int b = blockIdx.x, d = threadIdx.x;
    float s = 0.f;
#pragma unroll
    for (int q = 0; q < 16; q++) s += g_spart[(b * 16 + q) * ID + d];
    g_s[b * ID + d] = __float2half_rn(s);
}

// ---------------- wprep: W -> fp16 row-major + transposed (once) -------------
__global__ void __launch_bounds__(256) wprep_kernel(const float* __restrict__ W) {
    __shared__ __half Wts[256 * 72];
    const int n = blockIdx.x;
    const int t = threadIdx.x;
    const int p = t >> 3, seg = t & 7;

    const float* src = W + ((size_t)n * DC + 2 * p) * ID + seg * 32;
    float4 q0[8], q1[8];
#pragma unroll
    for (int r = 0; r < 8; r++) q0[r] = ((const float4*)src)[r];
#pragma unroll
    for (int r = 0; r < 8; r++) q1[r] = ((const float4*)(src + ID))[r];

    // row-major fp16
    {
        uint32_t ha[16], hb[16];
#pragma unroll
        for (int r = 0; r < 8; r++) {
            ha[2 * r]     = h2u(__floats2half2_rn(q0[r].x, q0[r].y));
            ha[2 * r + 1] = h2u(__floats2half2_rn(q0[r].z, q0[r].w));
            hb[2 * r]     = h2u(__floats2half2_rn(q1[r].x, q1[r].y));
            hb[2 * r + 1] = h2u(__floats2half2_rn(q1[r].z, q1[r].w));
        }
        uint4* d0 = (uint4*)(g_Whg + ((size_t)n * DC + 2 * p) * ID + seg * 32);
        uint4* d1 = (uint4*)(g_Whg + ((size_t)n * DC + 2 * p + 1) * ID + seg * 32);
#pragma unroll
        for (int q = 0; q < 4; q++) {
            d0[q] = make_uint4(ha[4 * q], ha[4 * q + 1], ha[4 * q + 2], ha[4 * q + 3]);
            d1[q] = make_uint4(hb[4 * q], hb[4 * q + 1], hb[4 * q + 2], hb[4 * q + 3]);
        }
    }

    // transposed via smem
#pragma unroll
    for (int r = 0; r < 8; r++) {
        const int d = seg * 32 + 4 * r;
        *(__half2*)&Wts[(d + 0) * 72 + 2 * p] = __floats2half2_rn(q0[r].x, q1[r].x);
        *(__half2*)&Wts[(d + 1) * 72 + 2 * p] = __floats2half2_rn(q0[r].y, q1[r].y);
        *(__half2*)&Wts[(d + 2) * 72 + 2 * p] = __floats2half2_rn(q0[r].z, q1[r].z);
        *(__half2*)&Wts[(d + 3) * 72 + 2 * p] = __floats2half2_rn(q0[r].w, q1[r].w);
    }
    __syncthreads();
    {
        const uint4* srow = (const uint4*)&Wts[t * 72];
        uint4* dst = (uint4*)(g_Wtg + ((size_t)n * ID + t) * DC);
#pragma unroll
        for (int q = 0; q < 8; q++) dst[q] = srow[q];
    }
}

// ---------------- projection: grid (NC, 4 bgroups), 16 batches/block ---------
// smem: Wh [64][264]h @0 | Wt [256][72]h @33792 | Vs [16][264]h @70656
//       Os [16][68]f @79104 | Oh [16][72]h @83456   (total 85760 B)
template <int PHASE>
__global__ void __launch_bounds__(256) proj_kernel(float* __restrict__ out) {
    extern __shared__ char sm[];
    __half* Wh = (__half*)sm;
    __half* Wt = (__half*)(sm + 33792);
    __half* Vs = (__half*)(sm + 70656);
    float*  Os = (float*)(sm + 79104);
    __half* Oh = (__half*)(sm + 83456);

    const int n = blockIdx.x, b_base = blockIdx.y * 16;
    const int t = threadIdx.x, w = t >> 5, l = t & 31;
    const int g = l >> 2, tig = l & 3;

    // copy W (both layouts) from precomputed fp16 globals
    {
        const uint4* src = (const uint4*)(g_Whg + ((size_t)n * DC + (t >> 2)) * ID + (t & 3) * 64);
        uint4* dst = (uint4*)&Wh[(t >> 2) * 264 + (t & 3) * 64];
#pragma unroll
        for (int q = 0; q < 8; q++) dst[q] = src[q];
    }
    {
        const uint4* src = (const uint4*)(g_Wtg + ((size_t)n * ID + t) * DC);
        uint4* dst = (uint4*)&Wt[t * 72];
#pragma unroll
        for (int q = 0; q < 8; q++) dst[q] = src[q];
    }

    // gather Vs [16 b][256 d]
    {
        const int bl = t >> 4, seg = t & 15;
        if (PHASE == 0) {
            const uint4* src = (const uint4*)(g_s + (b_base + bl) * ID + seg * 16);
            uint4* dst = (uint4*)&Vs[bl * 264 + seg * 16];
            dst[0] = src[0]; dst[1] = src[1];
        } else {
            float acc[16];
#pragma unroll
            for (int k = 0; k < 16; k++) acc[k] = 0.f;
#pragma unroll 4
            for (int ch = 0; ch < 16; ch++) {
                const float4* sp = (const float4*)(g_vpart +
                    (((size_t)(b_base + bl) * 16 + ch) * NC + n) * ID + seg * 16);
#pragma unroll
                for (int r = 0; r < 4; r++) {
                    float4 v = sp[r];
                    acc[4 * r] += v.x; acc[4 * r + 1] += v.y;
                    acc[4 * r + 2] += v.z; acc[4 * r + 3] += v.w;
                }
            }
            uint4* dst = (uint4*)&Vs[bl * 264 + seg * 16];
            dst[0] = make_uint4(h2u(__floats2half2_rn(acc[0], acc[1])),
                                h2u(__floats2half2_rn(acc[2], acc[3])),
                                h2u(__floats2half2_rn(acc[4], acc[5])),
                                h2u(__floats2half2_rn(acc[6], acc[7])));
            dst[1] = make_uint4(h2u(__floats2half2_rn(acc[8], acc[9])),
                                h2u(__floats2half2_rn(acc[10], acc[11])),
                                h2u(__floats2half2_rn(acc[12], acc[13])),
                                h2u(__floats2half2_rn(acc[14], acc[15])));
        }
    }
    __syncthreads();

    // mma1 (warps 0-3): O[16b, dc tile 16w..16w+15] = Vs x Wh
    if (w < 4) {
        float f1[2][4];
#pragma unroll
        for (int j = 0; j < 2; j++)
#pragma unroll
            for (int r = 0; r < 4; r++) f1[j][r] = 0.f;
        const uint32_t sA = s2u(Vs) + (l & 15) * 528 + (l >> 4) * 16;
        const uint32_t sB = s2u(Wh) + (16 * w + (l & 7) + 8 * (l >> 4)) * 528 + ((l >> 3) & 1) * 16;
#pragma unroll
        for (int ks = 0; ks < 16; ks++) {
            uint32_t a[4], bb[4];
            ldsm4(a, sA + ks * 32);
            ldsm4(bb, sB + ks * 32);
            mma_f16(f1[0], a, bb);
            mma_f16(f1[1], a, bb + 2);
        }
#pragma unroll
        for (int nt = 0; nt < 2; nt++) {
            const int dc0 = 16 * w + 8 * nt + 2 * tig;
            *(float2*)&Os[g * 68 + dc0] = make_float2(f1[nt][0], f1[nt][1]);
            *(float2*)&Os[(8 + g) * 68 + dc0] = make_float2(f1[nt][2], f1[nt][3]);
        }
    }
    __syncthreads();

    // norms: thread (bl = t>>4, c = t&15) covers 4 dc
    {
        const int bl = t >> 4, c = t & 15;
        float p2 = 0.f;
#pragma unroll
        for (int j = 0; j < 4; j++) {
            float v = Os[bl * 68 + 4 * c + j];
            p2 += v * v;
        }
        p2 += __shfl_xor_sync(0xffffffffu, p2, 1);
        p2 += __shfl_xor_sync(0xffffffffu, p2, 2);
        p2 += __shfl_xor_sync(0xffffffffu, p2, 4);
        p2 += __shfl_xor_sync(0xffffffffu, p2, 8);
        if (PHASE == 2) {
            float sq = p2 + 1e-7f;
            float sc = sqrtf(sq) / (0.5f + sq);
            float4 o4;
            o4.x = sc * Os[bl * 68 + 4 * c];
            o4.y = sc * Os[bl * 68 + 4 * c + 1];
            o4.z = sc * Os[bl * 68 + 4 * c + 2];
            o4.w = sc * Os[bl * 68 + 4 * c + 3];
            *(float4*)&out[((size_t)(b_base + bl) * NC + n) * DC + 4 * c] = o4;
            return;
        }
        const float inv = 1.0f / fmaxf(sqrtf(p2), 1e-12f);
        uint2 pk;
        pk.x = h2u(__floats2half2_rn(Os[bl * 68 + 4 * c] * inv, Os[bl * 68 + 4 * c + 1] * inv));
        pk.y = h2u(__floats2half2_rn(Os[bl * 68 + 4 * c + 2] * inv, Os[bl * 68 + 4 * c + 3] * inv));
        *(uint2*)&Oh[bl * 72 + 4 * c] = pk;
    }
    __syncthreads();

    // mma2 (all warps): w~[16b, d tile 32w..32w+31] = Oh x Wt
    {
        float f2[4][4];
#pragma unroll
        for (int j = 0; j < 4; j++)
#pragma unroll
            for (int r = 0; r < 4; r++) f2[j][r] = 0.f;
        const uint32_t sA2 = s2u(Oh) + (l & 15) * 144 + (l >> 4) * 16;
        const uint32_t sB2 = s2u(Wt) + (32 * w + (l & 7) + 8 * (l >> 4)) * 144 + ((l >> 3) & 1) * 16;
#pragma unroll
        for (int ks = 0; ks < 4; ks++) {
            uint32_t a[4], b0[4], b1[4];
            ldsm4(a, sA2 + ks * 32);
            ldsm4(b0, sB2 + ks * 32);
            ldsm4(b1, sB2 + 16 * 144 + ks * 32);
            mma_f16(f2[0], a, b0); mma_f16(f2[1], a, b0 + 2);
            mma_f16(f2[2], a, b1); mma_f16(f2[3], a, b1 + 2);
        }
#pragma unroll
        for (int nt = 0; nt < 4; nt++) {
            const int d0 = 32 * w + 8 * nt + 2 * tig;
            *(__half2*)&g_wtil[((size_t)(b_base + g) * NC + n) * ID + d0] =
                __floats2half2_rn(f2[nt][0], f2[nt][1]);
            *(__half2*)&g_wtil[((size_t)(b_base + 8 + g) * NC + n) * ID + d0] =
                __floats2half2_rn(f2[nt][2], f2[nt][3]);
        }
    }
}

// ---------------- fused routing: grid (16, 64), one 64-i chunk per block -----
// smem: uh [64][264]h @0 (33792) | wsh [32][264]h @33792 (16896)
//       csh [32][72]h @50688 (4608) | Lsh [64][34]f @55296 (8704) -> 64000 B
__global__ void __launch_bounds__(256, 3) fused_kernel() {
    extern __shared__ char smem[];
    __half* uh = (__half*)smem;
    __half* wsh = (__half*)(smem + 33792);
    __half* csh = (__half*)(smem + 50688);
    float* Lsh = (float*)(smem + 55296);

    const int b = blockIdx.y;
    const int i0 = blockIdx.x * 64;
    const int t = threadIdx.x, w = t >> 5, l = t & 31;
    const int g = l >> 2, tig = l & 3;

    // load w~
    {
        const int n = t >> 3, seg = t & 7;
        const uint4* wp = (const uint4*)(g_wtil + ((size_t)b * NC + n) * ID + seg * 32);
        uint4* ws = (uint4*)&wsh[n * 264 + seg * 32];
        ws[0] = wp[0]; ws[1] = wp[1]; ws[2] = wp[2]; ws[3] = wp[3];
    }
    // copy uh tile
    {
        const int i = t >> 2, c = t & 3;
        const uint4* src = (const uint4*)(g_uh + ((size_t)b * IN + i0 + i) * ID + c * 64);
        uint4* dst = (uint4*)&uh[i * 264 + c * 64];
#pragma unroll
        for (int q = 0; q < 8; q++) dst[q] = src[q];
    }
    __syncthreads();

    const int lA = l & 15;
    const int lAc = (l >> 4) * 16;
    const int lB = (l & 7) + 8 * (l >> 4);
    const int lBc = ((l >> 3) & 1) * 16;

    const uint32_t uhA = s2u(uh) + ((16 * (w >> 1) + lA) * 264) * 2 + lAc;
    const uint32_t wB  = s2u(wsh) + (((w & 1) * 16 + lB) * 264) * 2 + lBc;
    const uint32_t uhT = s2u(uh) + (lB * 264 + 32 * w) * 2 + lBc;
    const uint32_t cB  = s2u(csh) + (lB * 72) * 2 + lBc;

    // logits mma
    {
        float f[2][4];
#pragma unroll
        for (int nt = 0; nt < 2; nt++)
#pragma unroll
            for (int r = 0; r < 4; r++) f[nt][r] = 0.f;
#pragma unroll
        for (int ks = 0; ks < 16; ks++) {
            uint32_t a[4], bb[4];
            ldsm4(a, uhA + ks * 32);
            ldsm4(bb, wB + ks * 32);
            mma_f16(f[0], a, bb);
            mma_f16(f[1], a, bb + 2);
        }
        const int lmt = w >> 1, hh = w & 1;
#pragma unroll
        for (int nt = 0; nt < 2; nt++) {
            const int n0 = hh * 16 + nt * 8 + 2 * tig;
            *(float2*)&Lsh[(16 * lmt + g) * 34 + n0] = make_float2(f[nt][0], f[nt][1]);
            *(float2*)&Lsh[(16 * lmt + 8 + g) * 34 + n0] = make_float2(f[nt][2], f[nt][3]);
        }
    }
    __syncthreads();

    // softmax over n (lane = n); warp w: i rows 8w..8w+7
#pragma unroll
    for (int r8 = 0; r8 < 8; r8++) {
        const int r = w * 8 + r8;
        const float val = Lsh[r * 34 + l];
        float mx = val;
#pragma unroll
        for (int off = 16; off; off >>= 1)
            mx = fmaxf(mx, __shfl_xor_sync(0xffffffffu, mx, off));
        const float e = __expf(val - mx);
        float s = e;
#pragma unroll
        for (int off = 16; off; off >>= 1) s += __shfl_xor_sync(0xffffffffu, s, off);
        csh[l * 72 + r] = __float2half_rn(e / s);
    }
    __syncthreads();

    // accumulation mma: V[d,n] = sum_i uh^T[d,i] * c[n,i]
    float vfr[2][4][4];
#pragma unroll
    for (int s = 0; s < 2; s++)
#pragma unroll
        for (int nt = 0; nt < 4; nt++)
#pragma unroll
            for (int r = 0; r < 4; r++) vfr[s][nt][r] = 0.f;
#pragma unroll
    for (int ks = 0; ks < 4; ks++) {
        uint32_t a0[4], a1[4], c0[4], c1[4];
        ldsm4t(a0, uhT + ks * 8448);
        ldsm4t(a1, uhT + 32 + ks * 8448);
        ldsm4(c0, cB + ks * 32);
        ldsm4(c1, cB + 2304 + ks * 32);
        mma_f16(vfr[0][0], a0, c0); mma_f16(vfr[0][1], a0, c0 + 2);
        mma_f16(vfr[0][2], a0, c1); mma_f16(vfr[0][3], a0, c1 + 2);
        mma_f16(vfr[1][0], a1, c0); mma_f16(vfr[1][1], a1, c0 + 2);
        mma_f16(vfr[1][2], a1, c1); mma_f16(vfr[1][3], a1, c1 + 2);
    }

    // store V partials
    float* vp = g_vpart + (((size_t)b * 16 + blockIdx.x) * NC) * ID;
#pragma unroll
    for (int s = 0; s < 2; s++) {
        const int d0 = 32 * w + 16 * s + g;
#pragma unroll
        for (int nt = 0; nt < 4; nt++) {
            const int n0 = 8 * nt + 2 * tig;
            vp[(size_t)n0 * ID + d0] = vfr[s][nt][0];
            vp[(size_t)(n0 + 1) * ID + d0] = vfr[s][nt][1];
            vp[(size_t)n0 * ID + d0 + 8] = vfr[s][nt][2];
            vp[(size_t)(n0 + 1) * ID + d0 + 8] = vfr[s][nt][3];
        }
    }
}

// ---------------- launch ------------------------------------------------------
extern "C" void kernel_launch(void* const* d_in, const int* in_sizes, int n_in,
                              void* d_out, int out_size) {
    (void)in_sizes; (void)n_in; (void)out_size;
    const float* u = (const float*)d_in[0];   // [64, 1024, 256] fp32
    const float* W = (const float*)d_in[1];   // [2048, 256] fp32
    float* out = (float*)d_out;               // [64, 32, 64] fp32

    const int pbytes = 85760;   // proj smem
    const int fbytes = 64000;   // fused smem
    static int attr_done = 0;
    if (!attr_done) {
        cudaFuncSetAttribute(proj_kernel<0>, cudaFuncAttributeMaxDynamicSharedMemorySize, pbytes);
        cudaFuncSetAttribute(proj_kernel<1>, cudaFuncAttributeMaxDynamicSharedMemorySize, pbytes);
        cudaFuncSetAttribute(proj_kernel<2>, cudaFuncAttributeMaxDynamicSharedMemorySize, pbytes);
        cudaFuncSetAttribute(fused_kernel, cudaFuncAttributeMaxDynamicSharedMemorySize, fbytes);
        attr_done = 1;
    }

    prep_kernel<<<dim3(16, B), 256>>>(u);               // u -> fp16 + partials
    wprep_kernel<<<NC, 256>>>(W);                       // W -> fp16 x2 (once)
    colreduce_kernel<<<B, 256>>>();                     // colsum -> fp16
    proj_kernel<0><<<dim3(NC, 4), 256, pbytes>>>(out);  // o0 -> w~0
    fused_kernel<<<dim3(16, B), 256, fbytes>>>();       // iter 1 -> v1
    proj_kernel<1><<<dim3(NC, 4), 256, pbytes>>>(out);  // o1 -> w~1
    fused_kernel<<<dim3(16, B), 256, fbytes>>>();       // iter 2 -> v2
    proj_kernel<2><<<dim3(NC, 4), 256, pbytes>>>(out);  // squash -> out
}